// round 17
// baseline (speedup 1.0000x reference)
#include <cuda_runtime.h>
#include <cuda_fp16.h>

#define PN 4
#define LN 512
#define DN 64

#define L2E  1.4426950408889634f
#define LN2  0.6931471805599453f

// ---------------- device scratch (zero-init; winner resets after use) -------
__device__ __align__(16) float g_rs[PN * LN];   // row sum of exp2(v2)
__device__ __align__(16) float g_cs[PN * LN];   // col sum of exp2(v2)
__device__ float g_pn[PN], g_pd[PN];
__device__ volatile unsigned g_bar0;
__device__ unsigned g_tick;

// ============ single persistent kernel: 128 blocks, 512 thr, 64j x 128k ======
// d-pair fp16x2 packing: half2 lanes hold (d_even, d_odd) of the SAME (j,k).
// acc += hmin2(a,b) accumulates 2 d's/op; s = lo+hi at the end.  No operand
// duplication, no fp32 spill chunks (each lane sums only 32 d's, mag<=70).
// v2 = 2*L2E*acc - SA_j - SB_k (pre-scaled fp32), E = exp2(v2).
__global__ __launch_bounds__(512, 1) void k_all(const float* __restrict__ z,
                                                const float* __restrict__ wgt,
                                                const float* __restrict__ bias,
                                                float* __restrict__ out) {
    extern __shared__ char smraw[];
    __half2* z0h = (__half2*)smraw;               // [32 dp][68]  (a_2dp, a_2dp+1)
    __half2* z1h = (__half2*)smraw + 32 * 68;     // [32 dp][132] (b_2dp, b_2dp+1)
    __shared__ float part0[16][65];   // z0 d-quad row sums (fp32)
    __shared__ float part1[16][129];  // z1 d-quad row sums (fp32)
    __shared__ float sSA[64], sSB[128];   // pre-scaled by log2e
    __shared__ float scs[16][128];
    __shared__ float sAi[64], sBi[128];
    __shared__ float sn[16], sd[16];
    __shared__ int   s_win;

    const int kb = blockIdx.x, jb = blockIdx.y, p = blockIdx.z;
    const int t  = threadIdx.x;
    const int j0 = jb * 64, k0 = kb * 128;
    const int tx = t & 31, ty = t >> 5;         // lane, warp (= d-quad in prologue)

    const float4* z0g = (const float4*)(z + ((size_t)p * LN + j0) * DN);
    const float4* z1g = (const float4*)(z + ((size_t)(p + PN) * LN + k0) * DN);

    // ---- prologue: z0 -> d-pair half2 (j-major); d-quad row sums (fp32) ----
    #pragma unroll
    for (int i = 0; i < 2; i++) {
        int r = tx + 32 * i;                    // j row 0..63
        float4 v = z0g[r * 16 + ty];            // d = 4*ty .. 4*ty+3
        z0h[(2 * ty + 0) * 68 + r] = __floats2half2_rn(v.x, v.y);
        z0h[(2 * ty + 1) * 68 + r] = __floats2half2_rn(v.z, v.w);
        part0[ty][r] = (v.x + v.y) + (v.z + v.w);
    }
    // ---- prologue: z1 -> d-pair half2 (k-major) ----
    #pragma unroll
    for (int i = 0; i < 4; i++) {
        int r = tx + 32 * i;                    // k row 0..127
        float4 u = z1g[r * 16 + ty];
        z1h[(2 * ty + 0) * 132 + r] = __floats2half2_rn(u.x, u.y);
        z1h[(2 * ty + 1) * 132 + r] = __floats2half2_rn(u.z, u.w);
        part1[ty][r] = (u.x + u.y) + (u.z + u.w);
    }
    __syncthreads();

    // SA_j / SB_k (full d sums, pre-scaled by log2e)
    if (t < 64) {
        float s0 = 0.f;
        #pragma unroll
        for (int q = 0; q < 16; q++) s0 += part0[q][t];
        sSA[t] = s0 * L2E;
    } else if (t < 192) {
        int id = t - 64;
        float s1 = 0.f;
        #pragma unroll
        for (int q = 0; q < 16; q++) s1 += part1[q][id];
        sSB[id] = s1 * L2E;
    }

    // ---- mainloop: j = 4*ty..+3, k = 4*tx..+3; 32 d-pairs, no spills ----
    __half2 acch[4][4];
    #pragma unroll
    for (int jj = 0; jj < 4; jj++)
        #pragma unroll
        for (int i = 0; i < 4; i++) acch[jj][i] = __floats2half2_rn(0.f, 0.f);

    const __half2* z0b = z0h + 4 * ty;           // j-quad (4 half2 = 16B)
    const __half2* z1b = z1h + 4 * tx;           // k-quad (4 half2 = 16B)

    #pragma unroll 8
    for (int dp = 0; dp < 32; dp++) {
        uint4 araw = *(const uint4*)(z0b + dp * 68);   // broadcast LDS.128
        uint4 braw = *(const uint4*)(z1b + dp * 132);  // conflict-free LDS.128
        const __half2* av = (const __half2*)&araw;
        const __half2* bv = (const __half2*)&braw;
        #pragma unroll
        for (int jj = 0; jj < 4; jj++)
            #pragma unroll
            for (int i = 0; i < 4; i++)
                acch[jj][i] = __hadd2(acch[jj][i], __hmin2(av[jj], bv[i]));
    }
    __syncthreads();   // sSA/sSB written pre-mainloop by threads 0..191

    // ---- epilogue: v2 = 2*L2E*(lo+hi) - SA - SB;  E = exp2(v2) ----
    float v2[4][4], E[4][4];
    {
        float4 SAv = *(const float4*)&sSA[4 * ty];
        float4 SBv = *(const float4*)&sSB[4 * tx];
        const float SAj[4] = { SAv.x, SAv.y, SAv.z, SAv.w };
        const float SBk[4] = { SBv.x, SBv.y, SBv.z, SBv.w };
        #pragma unroll
        for (int jj = 0; jj < 4; jj++)
            #pragma unroll
            for (int i = 0; i < 4; i++) {
                float2 f = __half22float2(acch[jj][i]);
                float v = fmaf(2.0f * L2E, f.x + f.y, -(SAj[jj] + SBk[i]));
                v2[jj][i] = v;
                E[jj][i]  = exp2f(v);
            }
    }

    // ---- row sums (this block's 128 k, REDG across 4 kb) ----
    #pragma unroll
    for (int jj = 0; jj < 4; jj++) {
        float e = (E[jj][0] + E[jj][1]) + (E[jj][2] + E[jj][3]);
        #pragma unroll
        for (int o = 16; o; o >>= 1) e += __shfl_xor_sync(~0u, e, o);
        if (tx == 0)
            atomicAdd(&g_rs[p * LN + j0 + 4 * ty + jj], e);
    }

    // ---- col sums (block-local 64 j, REDG across 8 jb) ----
    {
        float c0 = 0, c1 = 0, c2 = 0, c3 = 0;
        #pragma unroll
        for (int jj = 0; jj < 4; jj++) {
            c0 += E[jj][0]; c1 += E[jj][1]; c2 += E[jj][2]; c3 += E[jj][3];
        }
        *(float4*)&scs[ty][4 * tx] = make_float4(c0, c1, c2, c3);
    }
    __syncthreads();
    if (t < 128) {
        float e = 0.f;
        #pragma unroll
        for (int q = 0; q < 16; q++) e += scs[q][t];
        atomicAdd(&g_cs[p * LN + k0 + t], e);
    }

    // ---- grid barrier (128 co-resident blocks) ----
    __threadfence();
    __syncthreads();
    if (t == 0) {
        atomicAdd((unsigned*)&g_bar0, 1u);
        while (g_bar0 < 128u) { }
    }
    __syncthreads();

    // ---- 1/rowsum, 1/colsum ----
    if (t < 64) {
        sAi[t] = 1.0f / __ldcg(&g_rs[p * LN + j0 + t]);
    } else if (t < 192) {
        int id = t - 64;
        sBi[id] = 1.0f / __ldcg(&g_cs[p * LN + k0 + id]);
    }
    __syncthreads();

    // ---- phase C: own-tile sum(c*v2), sum(c) ----
    {
        float4 Bv = *(const float4*)&sBi[4 * tx];
        const float Bk[4] = { Bv.x, Bv.y, Bv.z, Bv.w };
        float num = 0.f, den = 0.f;
        #pragma unroll
        for (int jj = 0; jj < 4; jj++) {
            float Aj = sAi[4 * ty + jj];         // broadcast
            #pragma unroll
            for (int i = 0; i < 4; i++) {
                float a = E[jj][i] * Aj;
                float b = E[jj][i] * Bk[i];
                float c = a + b - a * b;
                num = fmaf(c, v2[jj][i], num);
                den += c;
            }
        }
        #pragma unroll
        for (int o = 16; o; o >>= 1) {
            num += __shfl_xor_sync(~0u, num, o);
            den += __shfl_xor_sync(~0u, den, o);
        }
        if (tx == 0) { sn[ty] = num; sd[ty] = den; }
        __syncthreads();
        if (t == 0) {
            float N = 0.f, D = 0.f;
            #pragma unroll
            for (int q = 0; q < 16; q++) { N += sn[q]; D += sd[q]; }
            atomicAdd(&g_pn[p], N);
            atomicAdd(&g_pd[p], D);
        }
    }

    // ---- ticket: last block finalizes + resets ----
    __threadfence();
    __syncthreads();
    if (t == 0) s_win = (atomicAdd(&g_tick, 1u) == 127u) ? 1 : 0;
    __syncthreads();
    if (!s_win) return;

    if (t < 16) {
        int pp = t >> 2;
        float cv = (__ldcg(&g_pn[pp]) / __ldcg(&g_pd[pp])) * LN2;
        out[t] = cv * wgt[t & 3] + bias[t & 3];
    }
    __syncthreads();                             // reads done before resets
    #pragma unroll
    for (int i = 0; i < 4; i++) {                // reset accumulators for replay
        g_rs[i * 512 + t] = 0.f;
        g_cs[i * 512 + t] = 0.f;
    }
    if (t < PN) { g_pn[t] = 0.f; g_pd[t] = 0.f; }
    if (t == 0) { g_bar0 = 0; g_tick = 0; }
}

// ---------------- launch ----------------
extern "C" void kernel_launch(void* const* d_in, const int* in_sizes, int n_in,
                              void* d_out, int out_size) {
    const float* z = (const float*)d_in[0];   // (8, 512, 64) fp32
    const float* w = (const float*)d_in[1];   // (1, 4)
    const float* b = (const float*)d_in[2];   // (4,)
    float* out = (float*)d_out;               // (4, 4)

    const int smem = (68 + 132) * 32 * 4;     // 25600 B dynamic (half2 tiles)
    cudaFuncSetAttribute(k_all, cudaFuncAttributeMaxDynamicSharedMemorySize, smem);
    k_all<<<dim3(4, 8, 4), 512, smem>>>(z, w, b, out);
}